// round 2
// baseline (speedup 1.0000x reference)
#include <cuda_runtime.h>

#define N_NODES  50000
#define N_EDGES  1600000
#define IN_DIM   128
#define HID      64
#define N_GRAPHS 256

// ---------------- persistent scratch (no allocations allowed) ----------------
__device__ float g_h1[N_NODES * HID];     // GEMM output
__device__ float g_h2[N_NODES * HID];     // aggregate output / next GEMM input
__device__ float g_dinv[N_NODES];
__device__ int   g_deg[N_NODES];
__device__ int   g_off[N_NODES + 1];      // CSR offsets (by target node)
__device__ int   g_pos[N_NODES];          // running fill pointer for scatter
__device__ int   g_src[N_EDGES];          // CSR: source node per slot
__device__ float g_wgt[N_EDGES];          // CSR: dinv[r]*dinv[c] per slot
__device__ float g_psum[N_GRAPHS * HID];
__device__ float g_pcnt[N_GRAPHS];

// ---------------- setup kernels ----------------
__global__ void zero_deg_kernel() {
    int i = blockIdx.x * blockDim.x + threadIdx.x;
    if (i < N_NODES) g_deg[i] = 0;
}

__global__ void zero_pool_kernel() {
    int i = blockIdx.x * blockDim.x + threadIdx.x;
    if (i < N_GRAPHS * HID) g_psum[i] = 0.f;
    if (i < N_GRAPHS) g_pcnt[i] = 0.f;
}

__global__ void count_kernel(const int* __restrict__ ei) {
    int e = blockIdx.x * blockDim.x + threadIdx.x;
    if (e < N_EDGES) atomicAdd(&g_deg[ei[N_EDGES + e]], 1);
}

__global__ void dinv_kernel() {
    int i = blockIdx.x * blockDim.x + threadIdx.x;
    if (i < N_NODES) g_dinv[i] = rsqrtf((float)(g_deg[i] + 1));  // +1 self-loop
}

// Single-block exclusive prefix sum of g_deg -> g_off (and g_pos copy).
__global__ void scan_kernel() {
    __shared__ int s[1024];
    __shared__ int carry;
    if (threadIdx.x == 0) carry = 0;
    __syncthreads();
    for (int base = 0; base < N_NODES; base += 1024) {
        int i = base + (int)threadIdx.x;
        int v = (i < N_NODES) ? g_deg[i] : 0;
        s[threadIdx.x] = v;
        __syncthreads();
        #pragma unroll
        for (int d = 1; d < 1024; d <<= 1) {
            int t = (threadIdx.x >= (unsigned)d) ? s[threadIdx.x - d] : 0;
            __syncthreads();
            s[threadIdx.x] += t;
            __syncthreads();
        }
        int incl = s[threadIdx.x];
        int excl = incl - v;
        if (i < N_NODES) { g_off[i] = carry + excl; g_pos[i] = carry + excl; }
        __syncthreads();
        if (threadIdx.x == 1023) carry += s[1023];
        __syncthreads();
    }
    if (threadIdx.x == 0) g_off[N_NODES] = carry;
}

__global__ void scatter_kernel(const int* __restrict__ ei) {
    int e = blockIdx.x * blockDim.x + threadIdx.x;
    if (e >= N_EDGES) return;
    int r = ei[e];
    int c = ei[N_EDGES + e];
    int p = atomicAdd(&g_pos[c], 1);
    g_src[p] = r;
    g_wgt[p] = g_dinv[r] * g_dinv[c];
}

// ---------------- GEMM: H1[row,:] = X[row,:] @ W  (warp per row) ----------------
template<int K>
__global__ void __launch_bounds__(256) gemm_kernel(const float* __restrict__ Xext,
                                                   const float* __restrict__ W,
                                                   int use_h2) {
    __shared__ float Ws[K * HID];
    const float* X = use_h2 ? (const float*)g_h2 : Xext;
    for (int i = threadIdx.x; i < K * HID; i += blockDim.x) Ws[i] = W[i];
    __syncthreads();
    int gwarp = (blockIdx.x * blockDim.x + threadIdx.x) >> 5;
    int lane  = threadIdx.x & 31;
    int nw    = (gridDim.x * blockDim.x) >> 5;
    for (int row = gwarp; row < N_NODES; row += nw) {
        float ax = 0.f, ay = 0.f;
        const float* xr = X + (size_t)row * K;
        #pragma unroll
        for (int kb = 0; kb < K; kb += 32) {
            float xv = xr[kb + lane];
            #pragma unroll
            for (int j = 0; j < 32; j++) {
                float xk = __shfl_sync(0xffffffffu, xv, j);
                float2 w = *(const float2*)&Ws[(kb + j) * HID + 2 * lane];
                ax = fmaf(xk, w.x, ax);
                ay = fmaf(xk, w.y, ay);
            }
        }
        *(float2*)&g_h1[(size_t)row * HID + 2 * lane] = make_float2(ax, ay);
    }
}

// ---------------- Aggregate: H2[i] = relu(dinv[i]^2*H1[i] + sum_e w*H1[src] + b) ----------------
__global__ void __launch_bounds__(256) agg_kernel(const float* __restrict__ bias) {
    int gwarp = (blockIdx.x * blockDim.x + threadIdx.x) >> 5;
    int lane  = threadIdx.x & 31;
    int nw    = (gridDim.x * blockDim.x) >> 5;
    float bx = bias[2 * lane], by = bias[2 * lane + 1];
    for (int i = gwarp; i < N_NODES; i += nw) {
        float di = g_dinv[i];
        float sl = di * di;
        float2 h = *(const float2*)&g_h1[(size_t)i * HID + 2 * lane];
        float ax = sl * h.x, ay = sl * h.y;
        int s0 = g_off[i], s1 = g_off[i + 1];
        for (int p0 = s0; p0 < s1; p0 += 32) {
            int cnt = min(32, s1 - p0);
            int sidx = 0; float sw = 0.f;
            if (lane < cnt) { sidx = g_src[p0 + lane]; sw = g_wgt[p0 + lane]; }
            for (int j = 0; j < cnt; j++) {
                int   sj = __shfl_sync(0xffffffffu, sidx, j);
                float wj = __shfl_sync(0xffffffffu, sw,   j);
                float2 hv = *(const float2*)&g_h1[(size_t)sj * HID + 2 * lane];
                ax = fmaf(wj, hv.x, ax);
                ay = fmaf(wj, hv.y, ay);
            }
        }
        ax = fmaxf(ax + bx, 0.f);
        ay = fmaxf(ay + by, 0.f);
        *(float2*)&g_h2[(size_t)i * HID + 2 * lane] = make_float2(ax, ay);
    }
}

// ---------------- Pool: segment sums into g_psum / g_pcnt ----------------
__global__ void pool_kernel(const int* __restrict__ batch) {
    int t = blockIdx.x * blockDim.x + threadIdx.x;
    int node = t >> 5;
    int lane = t & 31;
    if (node >= N_NODES) return;
    int b = batch[node];
    float2 h = *(const float2*)&g_h2[(size_t)node * HID + 2 * lane];
    atomicAdd(&g_psum[b * HID + 2 * lane],     h.x);
    atomicAdd(&g_psum[b * HID + 2 * lane + 1], h.y);
    if (lane == 0) atomicAdd(&g_pcnt[b], 1.f);
}

// ---------------- Head: out[g] = (mean_g @ Wl1 + bl1) @ Wl2 + bl2 ----------------
__global__ void head_kernel(const float* __restrict__ Wl1, const float* __restrict__ bl1,
                            const float* __restrict__ Wl2, const float* __restrict__ bl2,
                            float* __restrict__ out) {
    __shared__ float w1[HID * 16];
    __shared__ float w2[16];
    int t = threadIdx.x;
    for (int i = t; i < HID * 16; i += blockDim.x) w1[i] = Wl1[i];
    if (t < 16) w2[t] = Wl2[t];
    __syncthreads();
    if (t < N_GRAPHS) {
        float inv = 1.f / fmaxf(g_pcnt[t], 1.f);
        float hid[16];
        #pragma unroll
        for (int j = 0; j < 16; j++) hid[j] = bl1[j];
        for (int k = 0; k < HID; k++) {
            float gv = g_psum[t * HID + k] * inv;
            #pragma unroll
            for (int j = 0; j < 16; j++) hid[j] = fmaf(gv, w1[k * 16 + j], hid[j]);
        }
        float o = bl2[0];
        #pragma unroll
        for (int j = 0; j < 16; j++) o = fmaf(hid[j], w2[j], o);
        out[t] = o;
    }
}

// ---------------- launch ----------------
extern "C" void kernel_launch(void* const* d_in, const int* in_sizes, int n_in,
                              void* d_out, int out_size) {
    const float* x     = (const float*)d_in[0];
    const int*   ei    = (const int*)d_in[1];     // JAX canonicalizes int64 -> int32
    const int*   batch = (const int*)d_in[2];
    const float* W1  = (const float*)d_in[3];  const float* b1  = (const float*)d_in[4];
    const float* W2  = (const float*)d_in[5];  const float* b2  = (const float*)d_in[6];
    const float* W3  = (const float*)d_in[7];  const float* b3  = (const float*)d_in[8];
    const float* Wl1 = (const float*)d_in[9];  const float* bl1 = (const float*)d_in[10];
    const float* Wl2 = (const float*)d_in[11]; const float* bl2 = (const float*)d_in[12];
    float* out = (float*)d_out;

    const int TB = 256;
    const int nodeBlocks = (N_NODES + TB - 1) / TB;
    const int edgeBlocks = (N_EDGES + TB - 1) / TB;
    const int warpBlocks = (N_NODES * 32 + TB - 1) / TB;   // warp per node

    // Build CSR (by target) + symmetric norm weights — once per launch
    zero_deg_kernel<<<nodeBlocks, TB>>>();
    count_kernel<<<edgeBlocks, TB>>>(ei);
    dinv_kernel<<<nodeBlocks, TB>>>();
    scan_kernel<<<1, 1024>>>();
    scatter_kernel<<<edgeBlocks, TB>>>(ei);

    // Layer 1
    gemm_kernel<IN_DIM><<<warpBlocks, TB>>>(x, W1, 0);
    agg_kernel<<<warpBlocks, TB>>>(b1);
    // Layer 2
    gemm_kernel<HID><<<warpBlocks, TB>>>(nullptr, W2, 1);
    agg_kernel<<<warpBlocks, TB>>>(b2);
    // Layer 3
    gemm_kernel<HID><<<warpBlocks, TB>>>(nullptr, W3, 1);
    agg_kernel<<<warpBlocks, TB>>>(b3);

    // Pool + head
    zero_pool_kernel<<<(N_GRAPHS * HID + TB - 1) / TB, TB>>>();
    pool_kernel<<<warpBlocks, TB>>>(batch);
    head_kernel<<<1, 256>>>(Wl1, bl1, Wl2, bl2, out);
}

// round 5
// speedup vs baseline: 1.5161x; 1.5161x over previous
#include <cuda_runtime.h>

#define N_NODES  50000
#define N_EDGES  1600000
#define IN_DIM   128
#define HID      64
#define N_GRAPHS 256
#define SCAN_B   1024
#define NBLK     ((N_NODES + SCAN_B - 1) / SCAN_B)   // 49

// ---------------- persistent scratch (no allocations allowed) ----------------
__device__ float g_h1[N_NODES * HID];     // GEMM output
__device__ float g_h2[N_NODES * HID];     // aggregate output / next GEMM input
__device__ float g_dinv[N_NODES];
__device__ int   g_deg[N_NODES];
__device__ int   g_off[N_NODES + 1];      // CSR offsets (by target node)
__device__ int   g_pos[N_NODES];          // running fill pointer for scatter
__device__ int   g_src[N_EDGES];          // CSR: source node per slot
__device__ float g_wgt[N_EDGES];          // CSR: dinv[r]*dinv[c] per slot
__device__ int   g_bsum[NBLK];            // per-block degree sums
__device__ int   g_boff[NBLK];            // exclusive scan of block sums
__device__ float g_psum[N_GRAPHS * HID];
__device__ float g_pcnt[N_GRAPHS];

// ---------------- setup kernels ----------------
__global__ void zero_deg_kernel() {
    int i = blockIdx.x * blockDim.x + threadIdx.x;
    if (i < N_NODES) g_deg[i] = 0;
}

__global__ void zero_pool_kernel() {
    int i = blockIdx.x * blockDim.x + threadIdx.x;
    if (i < N_GRAPHS * HID) g_psum[i] = 0.f;
    if (i < N_GRAPHS) g_pcnt[i] = 0.f;
}

__global__ void count_kernel(const int* __restrict__ ei) {
    int e = blockIdx.x * blockDim.x + threadIdx.x;
    if (e < N_EDGES) atomicAdd(&g_deg[ei[N_EDGES + e]], 1);
}

__global__ void dinv_kernel() {
    int i = blockIdx.x * blockDim.x + threadIdx.x;
    if (i < N_NODES) g_dinv[i] = rsqrtf((float)(g_deg[i] + 1));  // +1 self-loop
}

// ---- two-level scan: (1) block sums, (2) scan 49 sums, (3) block scan + base ----
__global__ void blocksum_kernel() {
    int i = blockIdx.x * SCAN_B + threadIdx.x;
    int v = (i < N_NODES) ? g_deg[i] : 0;
    #pragma unroll
    for (int d = 16; d > 0; d >>= 1) v += __shfl_down_sync(0xffffffffu, v, d);
    __shared__ int ws[32];
    int wid = threadIdx.x >> 5, lane = threadIdx.x & 31;
    if (lane == 0) ws[wid] = v;
    __syncthreads();
    if (wid == 0) {
        int s = ws[lane];
        #pragma unroll
        for (int d = 16; d > 0; d >>= 1) s += __shfl_down_sync(0xffffffffu, s, d);
        if (lane == 0) g_bsum[blockIdx.x] = s;
    }
}

__global__ void scanb_kernel() {
    // single warp scans NBLK (<=64) block sums
    int t = threadIdx.x;  // 64 threads
    __shared__ int s[64];
    int v = (t < NBLK) ? g_bsum[t] : 0;
    s[t] = v;
    __syncthreads();
    #pragma unroll
    for (int d = 1; d < 64; d <<= 1) {
        int u = (t >= d) ? s[t - d] : 0;
        __syncthreads();
        s[t] += u;
        __syncthreads();
    }
    if (t < NBLK) g_boff[t] = s[t] - v;          // exclusive
    if (t == NBLK - 1) g_off[N_NODES] = s[t];    // total edges
}

__global__ void fill_off_kernel() {
    int i = blockIdx.x * SCAN_B + threadIdx.x;
    int v = (i < N_NODES) ? g_deg[i] : 0;
    int lane = threadIdx.x & 31, wid = threadIdx.x >> 5;
    // warp inclusive scan
    int incl = v;
    #pragma unroll
    for (int d = 1; d < 32; d <<= 1) {
        int u = __shfl_up_sync(0xffffffffu, incl, d);
        if (lane >= d) incl += u;
    }
    __shared__ int wsum[32];
    if (lane == 31) wsum[wid] = incl;
    __syncthreads();
    if (wid == 0) {
        int s = wsum[lane];
        #pragma unroll
        for (int d = 1; d < 32; d <<= 1) {
            int u = __shfl_up_sync(0xffffffffu, s, d);
            if (lane >= d) s += u;
        }
        wsum[lane] = s - (lane == 31 ? 0 : 0);   // inclusive warp sums
        wsum[lane] = s;
        __syncthreads();
    } else {
        __syncthreads();
    }
    int warpbase = (wid > 0) ? wsum[wid - 1] : 0;
    int excl = incl - v + warpbase + g_boff[blockIdx.x];
    if (i < N_NODES) { g_off[i] = excl; g_pos[i] = excl; }
}

__global__ void scatter_kernel(const int* __restrict__ ei) {
    int e = blockIdx.x * blockDim.x + threadIdx.x;
    if (e >= N_EDGES) return;
    int r = ei[e];
    int c = ei[N_EDGES + e];
    int p = atomicAdd(&g_pos[c], 1);
    g_src[p] = r;
    g_wgt[p] = g_dinv[r] * g_dinv[c];
}

// ---------------- GEMM: H1 = X @ W, warp handles 4 rows ----------------
template<int K>
__global__ void __launch_bounds__(256) gemm_kernel(const float* __restrict__ Xext,
                                                   const float* __restrict__ W,
                                                   int use_h2) {
    __shared__ float Ws[K * HID];
    const float* X = use_h2 ? (const float*)g_h2 : Xext;
    for (int i = threadIdx.x; i < K * HID; i += 256) Ws[i] = W[i];
    __syncthreads();
    int gwarp = (blockIdx.x * 256 + threadIdx.x) >> 5;
    int lane  = threadIdx.x & 31;
    int nw    = (gridDim.x * 256) >> 5;
    const int NGRP = N_NODES / 4;   // 12500, exact
    for (int grp = gwarp; grp < NGRP; grp += nw) {
        int row = grp * 4;
        float a00 = 0.f, a01 = 0.f, a10 = 0.f, a11 = 0.f;
        float a20 = 0.f, a21 = 0.f, a30 = 0.f, a31 = 0.f;
        const float* xr = X + (size_t)row * K;
        #pragma unroll
        for (int kb = 0; kb < K; kb += 32) {
            float xv0 = xr[0 * K + kb + lane];
            float xv1 = xr[1 * K + kb + lane];
            float xv2 = xr[2 * K + kb + lane];
            float xv3 = xr[3 * K + kb + lane];
            #pragma unroll
            for (int j = 0; j < 32; j++) {
                float2 w = *(const float2*)&Ws[(kb + j) * HID + 2 * lane];
                float x0 = __shfl_sync(0xffffffffu, xv0, j);
                float x1 = __shfl_sync(0xffffffffu, xv1, j);
                float x2 = __shfl_sync(0xffffffffu, xv2, j);
                float x3 = __shfl_sync(0xffffffffu, xv3, j);
                a00 = fmaf(x0, w.x, a00); a01 = fmaf(x0, w.y, a01);
                a10 = fmaf(x1, w.x, a10); a11 = fmaf(x1, w.y, a11);
                a20 = fmaf(x2, w.x, a20); a21 = fmaf(x2, w.y, a21);
                a30 = fmaf(x3, w.x, a30); a31 = fmaf(x3, w.y, a31);
            }
        }
        *(float2*)&g_h1[(size_t)(row + 0) * HID + 2 * lane] = make_float2(a00, a01);
        *(float2*)&g_h1[(size_t)(row + 1) * HID + 2 * lane] = make_float2(a10, a11);
        *(float2*)&g_h1[(size_t)(row + 2) * HID + 2 * lane] = make_float2(a20, a21);
        *(float2*)&g_h1[(size_t)(row + 3) * HID + 2 * lane] = make_float2(a30, a31);
    }
}

// ------ Aggregate: H2[i] = relu(dinv^2*H1[i] + sum w*H1[src] + b); optional fused pool ------
__global__ void __launch_bounds__(256) agg_kernel(const float* __restrict__ bias,
                                                  const int* __restrict__ batch,
                                                  int do_pool) {
    int gwarp = (blockIdx.x * blockDim.x + threadIdx.x) >> 5;
    int lane  = threadIdx.x & 31;
    int nw    = (gridDim.x * blockDim.x) >> 5;
    float bx = bias[2 * lane], by = bias[2 * lane + 1];
    for (int i = gwarp; i < N_NODES; i += nw) {
        float di = g_dinv[i];
        float sl = di * di;
        float2 h = *(const float2*)&g_h1[(size_t)i * HID + 2 * lane];
        float ax = sl * h.x, ay = sl * h.y;
        int s0 = g_off[i], s1 = g_off[i + 1];
        for (int p0 = s0; p0 < s1; p0 += 32) {
            int cnt = min(32, s1 - p0);
            int sidx = 0; float sw = 0.f;
            if (lane < cnt) { sidx = g_src[p0 + lane]; sw = g_wgt[p0 + lane]; }
            for (int j = 0; j < cnt; j++) {
                int   sj = __shfl_sync(0xffffffffu, sidx, j);
                float wj = __shfl_sync(0xffffffffu, sw,   j);
                float2 hv = *(const float2*)&g_h1[(size_t)sj * HID + 2 * lane];
                ax = fmaf(wj, hv.x, ax);
                ay = fmaf(wj, hv.y, ay);
            }
        }
        ax = fmaxf(ax + bx, 0.f);
        ay = fmaxf(ay + by, 0.f);
        if (do_pool) {
            int b = batch[i];
            atomicAdd(&g_psum[b * HID + 2 * lane],     ax);
            atomicAdd(&g_psum[b * HID + 2 * lane + 1], ay);
            if (lane == 0) atomicAdd(&g_pcnt[b], 1.f);
        } else {
            *(float2*)&g_h2[(size_t)i * HID + 2 * lane] = make_float2(ax, ay);
        }
    }
}

// ---------------- Head: out[g] = (mean_g @ Wl1 + bl1) @ Wl2 + bl2 ----------------
__global__ void head_kernel(const float* __restrict__ Wl1, const float* __restrict__ bl1,
                            const float* __restrict__ Wl2, const float* __restrict__ bl2,
                            float* __restrict__ out) {
    __shared__ float w1[HID * 16];
    __shared__ float w2[16];
    int t = threadIdx.x;
    for (int i = t; i < HID * 16; i += blockDim.x) w1[i] = Wl1[i];
    if (t < 16) w2[t] = Wl2[t];
    __syncthreads();
    if (t < N_GRAPHS) {
        float inv = 1.f / fmaxf(g_pcnt[t], 1.f);
        float hid[16];
        #pragma unroll
        for (int j = 0; j < 16; j++) hid[j] = bl1[j];
        for (int k = 0; k < HID; k++) {
            float gv = g_psum[t * HID + k] * inv;
            #pragma unroll
            for (int j = 0; j < 16; j++) hid[j] = fmaf(gv, w1[k * 16 + j], hid[j]);
        }
        float o = bl2[0];
        #pragma unroll
        for (int j = 0; j < 16; j++) o = fmaf(hid[j], w2[j], o);
        out[t] = o;
    }
}

// ---------------- launch ----------------
extern "C" void kernel_launch(void* const* d_in, const int* in_sizes, int n_in,
                              void* d_out, int out_size) {
    const float* x     = (const float*)d_in[0];
    const int*   ei    = (const int*)d_in[1];     // JAX canonicalizes int64 -> int32
    const int*   batch = (const int*)d_in[2];
    const float* W1  = (const float*)d_in[3];  const float* b1  = (const float*)d_in[4];
    const float* W2  = (const float*)d_in[5];  const float* b2  = (const float*)d_in[6];
    const float* W3  = (const float*)d_in[7];  const float* b3  = (const float*)d_in[8];
    const float* Wl1 = (const float*)d_in[9];  const float* bl1 = (const float*)d_in[10];
    const float* Wl2 = (const float*)d_in[11]; const float* bl2 = (const float*)d_in[12];
    float* out = (float*)d_out;

    const int TB = 256;
    const int nodeBlocks = (N_NODES + TB - 1) / TB;
    const int edgeBlocks = (N_EDGES + TB - 1) / TB;
    const int warpBlocks = (N_NODES * 32 + TB - 1) / TB;   // warp per node
    const int gemmBlocks = ((N_NODES / 4) * 32 + TB - 1) / TB;

    // Build CSR (by target) + symmetric norm weights — once per launch
    zero_deg_kernel<<<nodeBlocks, TB>>>();
    zero_pool_kernel<<<(N_GRAPHS * HID + TB - 1) / TB, TB>>>();
    count_kernel<<<edgeBlocks, TB>>>(ei);
    dinv_kernel<<<nodeBlocks, TB>>>();
    blocksum_kernel<<<NBLK, SCAN_B>>>();
    scanb_kernel<<<1, 64>>>();
    fill_off_kernel<<<NBLK, SCAN_B>>>();
    scatter_kernel<<<edgeBlocks, TB>>>(ei);

    // Layer 1
    gemm_kernel<IN_DIM><<<gemmBlocks, TB>>>(x, W1, 0);
    agg_kernel<<<warpBlocks, TB>>>(b1, batch, 0);
    // Layer 2
    gemm_kernel<HID><<<gemmBlocks, TB>>>(nullptr, W2, 1);
    agg_kernel<<<warpBlocks, TB>>>(b2, batch, 0);
    // Layer 3 (pool fused)
    gemm_kernel<HID><<<gemmBlocks, TB>>>(nullptr, W3, 1);
    agg_kernel<<<warpBlocks, TB>>>(b3, batch, 1);

    // Head
    head_kernel<<<1, 256>>>(Wl1, bl1, Wl2, bl2, out);
}